// round 1
// baseline (speedup 1.0000x reference)
#include <cuda_runtime.h>
#include <math.h>

#define D_MODEL   1024
#define NUM_HEADS 16
#define DEPTH     64
#define BATCH     4
#define SEQ       2048
#define NROWS     (BATCH * SEQ)   // 8192

// Scratch (allocation-free): head-split Q/K/V [B*H, S, DEPTH] and merged context [B*S, D_MODEL]
__device__ float g_qh[(size_t)NROWS * D_MODEL];
__device__ float g_kh[(size_t)NROWS * D_MODEL];
__device__ float g_vh[(size_t)NROWS * D_MODEL];
__device__ float g_ctx[(size_t)NROWS * D_MODEL];

// ---------------------------------------------------------------------------
// GEMM + bias: C = A[N x 1024] @ W[1024 x 1024] + b
// 128x128 block tile, BK=8, 256 threads, 8x8 per thread.
// HEADOUT=1: store into head-split layout [(b*H+h)*S + s][d]
// HEADOUT=0: plain row-major [n][c]
// ---------------------------------------------------------------------------
template <int HEADOUT>
__global__ __launch_bounds__(256, 2)
void gemm_bias_128(const float* __restrict__ A, const float* __restrict__ W,
                   const float* __restrict__ bias, float* __restrict__ C) {
    __shared__ float As[8][132];   // [k][m], 132*4B = 528B row -> float4-aligned
    __shared__ float Bs[8][132];   // [k][n]

    const int tid = threadIdx.x;
    const int tx = tid & 15;       // 0..15 -> col group
    const int ty = tid >> 4;       // 0..15 -> row group
    const int row0 = blockIdx.y * 128;
    const int col0 = blockIdx.x * 128;

    float acc[8][8];
#pragma unroll
    for (int i = 0; i < 8; i++)
#pragma unroll
        for (int j = 0; j < 8; j++) acc[i][j] = 0.0f;

    for (int k0 = 0; k0 < D_MODEL; k0 += 8) {
        // Load A tile (128 rows x 8 k), transposed into As[k][m]
        {
            const int r  = tid >> 1;          // 0..127
            const int kq = (tid & 1) << 2;    // 0 or 4
            float4 v = *(const float4*)&A[(size_t)(row0 + r) * D_MODEL + k0 + kq];
            As[kq + 0][r] = v.x;
            As[kq + 1][r] = v.y;
            As[kq + 2][r] = v.z;
            As[kq + 3][r] = v.w;
        }
        // Load W tile (8 k x 128 cols)
        {
            const int kr = tid >> 5;          // 0..7
            const int cq = (tid & 31) << 2;   // 0..124
            float4 v = *(const float4*)&W[(size_t)(k0 + kr) * D_MODEL + col0 + cq];
            *(float4*)&Bs[kr][cq] = v;
        }
        __syncthreads();

#pragma unroll
        for (int kk = 0; kk < 8; kk++) {
            float a[8], b[8];
            *(float4*)&a[0] = *(const float4*)&As[kk][ty * 8];
            *(float4*)&a[4] = *(const float4*)&As[kk][ty * 8 + 4];
            *(float4*)&b[0] = *(const float4*)&Bs[kk][tx * 8];
            *(float4*)&b[4] = *(const float4*)&Bs[kk][tx * 8 + 4];
#pragma unroll
            for (int i = 0; i < 8; i++)
#pragma unroll
                for (int j = 0; j < 8; j++) acc[i][j] += a[i] * b[j];
        }
        __syncthreads();
    }

    // Epilogue: bias + store
#pragma unroll
    for (int i = 0; i < 8; i++) {
        const int r = row0 + ty * 8 + i;
#pragma unroll
        for (int jq = 0; jq < 8; jq += 4) {
            const int c = col0 + tx * 8 + jq;
            float4 o;
            o.x = acc[i][jq + 0] + bias[c + 0];
            o.y = acc[i][jq + 1] + bias[c + 1];
            o.z = acc[i][jq + 2] + bias[c + 2];
            o.w = acc[i][jq + 3] + bias[c + 3];
            if (HEADOUT) {
                const int b = r >> 11;          // / SEQ
                const int s = r & (SEQ - 1);
                const int h = c >> 6;           // / DEPTH
                const int d = c & (DEPTH - 1);  // 0..60, float4 stays inside head
                *(float4*)&C[((size_t)(b * NUM_HEADS + h) * SEQ + s) * DEPTH + d] = o;
            } else {
                *(float4*)&C[(size_t)r * D_MODEL + c] = o;
            }
        }
    }
}

// ---------------------------------------------------------------------------
// Flash attention: one block handles 64 queries of one (b,h).
// 256 threads (16x16), thread tile 4x4. Online softmax over 32 key tiles.
// Smem: Qs^T[64d][68], Ks^T[64d][68], Vs[64c][68], Ps[64r][68]  = 69632 B
// ---------------------------------------------------------------------------
__global__ __launch_bounds__(256, 2)
void attn64(const float* __restrict__ qh, const float* __restrict__ kh,
            const float* __restrict__ vh, float* __restrict__ ctx) {
    extern __shared__ float sm[];
    float* Qs = sm;               // Qs[d*68 + r]
    float* Ks = Qs + 64 * 68;     // Ks[d*68 + c]
    float* Vs = Ks + 64 * 68;     // Vs[c*68 + d]
    float* Ps = Vs + 64 * 68;     // Ps[r*68 + c]

    const int tid = threadIdx.x;
    const int tx = tid & 15;
    const int ty = tid >> 4;
    const int bh = blockIdx.y;            // b*NUM_HEADS + h
    const int q0 = blockIdx.x * 64;

    const float* Qb = qh + (size_t)bh * SEQ * DEPTH;
    const float* Kb = kh + (size_t)bh * SEQ * DEPTH;
    const float* Vb = vh + (size_t)bh * SEQ * DEPTH;

    // Load Q tile transposed (once)
#pragma unroll
    for (int it = 0; it < 4; it++) {
        const int idx = tid + it * 256;
        const int r  = idx >> 4;          // 0..63
        const int dq = (idx & 15) << 2;   // 0..60
        float4 v = *(const float4*)&Qb[(size_t)(q0 + r) * DEPTH + dq];
        Qs[(dq + 0) * 68 + r] = v.x;
        Qs[(dq + 1) * 68 + r] = v.y;
        Qs[(dq + 2) * 68 + r] = v.z;
        Qs[(dq + 3) * 68 + r] = v.w;
    }

    float m_[4], l_[4], o_[4][4];
#pragma unroll
    for (int i = 0; i < 4; i++) {
        m_[i] = -1e30f;
        l_[i] = 0.0f;
#pragma unroll
        for (int j = 0; j < 4; j++) o_[i][j] = 0.0f;
    }

    const float scale = 0.125f;  // 1/sqrt(64)

    for (int k0 = 0; k0 < SEQ; k0 += 64) {
        __syncthreads();  // protect Ks/Vs (prev S-compute) and Ps (prev PV)

        // Load K tile transposed + V tile natural
#pragma unroll
        for (int it = 0; it < 4; it++) {
            const int idx = tid + it * 256;
            const int c  = idx >> 4;
            const int dq = (idx & 15) << 2;
            float4 kv = *(const float4*)&Kb[(size_t)(k0 + c) * DEPTH + dq];
            Ks[(dq + 0) * 68 + c] = kv.x;
            Ks[(dq + 1) * 68 + c] = kv.y;
            Ks[(dq + 2) * 68 + c] = kv.z;
            Ks[(dq + 3) * 68 + c] = kv.w;
            float4 vv = *(const float4*)&Vb[(size_t)(k0 + c) * DEPTH + dq];
            *(float4*)&Vs[c * 68 + dq] = vv;
        }
        __syncthreads();

        // S = Q K^T (4x4 per thread)
        float s_[4][4];
#pragma unroll
        for (int i = 0; i < 4; i++)
#pragma unroll
            for (int j = 0; j < 4; j++) s_[i][j] = 0.0f;

#pragma unroll
        for (int d = 0; d < 64; d++) {
            float4 a = *(const float4*)&Qs[d * 68 + (ty << 2)];
            float4 b = *(const float4*)&Ks[d * 68 + (tx << 2)];
            s_[0][0] += a.x * b.x; s_[0][1] += a.x * b.y; s_[0][2] += a.x * b.z; s_[0][3] += a.x * b.w;
            s_[1][0] += a.y * b.x; s_[1][1] += a.y * b.y; s_[1][2] += a.y * b.z; s_[1][3] += a.y * b.w;
            s_[2][0] += a.z * b.x; s_[2][1] += a.z * b.y; s_[2][2] += a.z * b.z; s_[2][3] += a.z * b.w;
            s_[3][0] += a.w * b.x; s_[3][1] += a.w * b.y; s_[3][2] += a.w * b.z; s_[3][3] += a.w * b.w;
        }

        // Online softmax update (row groups of 16 lanes share a row set)
#pragma unroll
        for (int i = 0; i < 4; i++) {
            float v0 = s_[i][0] * scale;
            float v1 = s_[i][1] * scale;
            float v2 = s_[i][2] * scale;
            float v3 = s_[i][3] * scale;
            float rmax = fmaxf(fmaxf(v0, v1), fmaxf(v2, v3));
#pragma unroll
            for (int off = 8; off > 0; off >>= 1)
                rmax = fmaxf(rmax, __shfl_xor_sync(0xffffffffu, rmax, off));
            const float mnew = fmaxf(m_[i], rmax);
            const float corr = __expf(m_[i] - mnew);
            m_[i] = mnew;
            const float p0 = __expf(v0 - mnew);
            const float p1 = __expf(v1 - mnew);
            const float p2 = __expf(v2 - mnew);
            const float p3 = __expf(v3 - mnew);
            float rsum = p0 + p1 + p2 + p3;
#pragma unroll
            for (int off = 8; off > 0; off >>= 1)
                rsum += __shfl_xor_sync(0xffffffffu, rsum, off);
            l_[i] = l_[i] * corr + rsum;
#pragma unroll
            for (int j = 0; j < 4; j++) o_[i][j] *= corr;
            *(float4*)&Ps[(ty * 4 + i) * 68 + tx * 4] = make_float4(p0, p1, p2, p3);
        }
        __syncthreads();

        // O += P V
#pragma unroll
        for (int c = 0; c < 64; c++) {
            float4 b = *(const float4*)&Vs[c * 68 + (tx << 2)];
            float a0 = Ps[(ty * 4 + 0) * 68 + c];
            float a1 = Ps[(ty * 4 + 1) * 68 + c];
            float a2 = Ps[(ty * 4 + 2) * 68 + c];
            float a3 = Ps[(ty * 4 + 3) * 68 + c];
            o_[0][0] += a0 * b.x; o_[0][1] += a0 * b.y; o_[0][2] += a0 * b.z; o_[0][3] += a0 * b.w;
            o_[1][0] += a1 * b.x; o_[1][1] += a1 * b.y; o_[1][2] += a1 * b.z; o_[1][3] += a1 * b.w;
            o_[2][0] += a2 * b.x; o_[2][1] += a2 * b.y; o_[2][2] += a2 * b.z; o_[2][3] += a2 * b.w;
            o_[3][0] += a3 * b.x; o_[3][1] += a3 * b.y; o_[3][2] += a3 * b.z; o_[3][3] += a3 * b.w;
        }
    }

    // Finalize: divide by l, merge heads into ctx [B*S, D_MODEL]
    const int b = bh >> 4;          // / NUM_HEADS
    const int h = bh & 15;
#pragma unroll
    for (int i = 0; i < 4; i++) {
        const int srow = q0 + ty * 4 + i;
        const float inv = 1.0f / l_[i];
        float4 o;
        o.x = o_[i][0] * inv;
        o.y = o_[i][1] * inv;
        o.z = o_[i][2] * inv;
        o.w = o_[i][3] * inv;
        *(float4*)&g_ctx[((size_t)(b * SEQ + srow)) * D_MODEL + h * DEPTH + (tx << 2)] = o;
    }
    (void)ctx;
}

// ---------------------------------------------------------------------------
extern "C" void kernel_launch(void* const* d_in, const int* in_sizes, int n_in,
                              void* d_out, int out_size) {
    const float* v  = (const float*)d_in[0];
    const float* k  = (const float*)d_in[1];
    const float* q  = (const float*)d_in[2];
    const float* wq = (const float*)d_in[3];
    const float* bq = (const float*)d_in[4];
    const float* wk = (const float*)d_in[5];
    const float* bk = (const float*)d_in[6];
    const float* wv = (const float*)d_in[7];
    const float* bv = (const float*)d_in[8];
    const float* wo = (const float*)d_in[9];
    const float* bo = (const float*)d_in[10];
    float* out = (float*)d_out;

    float *qh, *kh, *vh, *ctx;
    cudaGetSymbolAddress((void**)&qh, g_qh);
    cudaGetSymbolAddress((void**)&kh, g_kh);
    cudaGetSymbolAddress((void**)&vh, g_vh);
    cudaGetSymbolAddress((void**)&ctx, g_ctx);

    const dim3 blk(256);
    const dim3 gp(D_MODEL / 128, NROWS / 128);   // (8, 64)

    gemm_bias_128<1><<<gp, blk>>>(q, wq, bq, qh);
    gemm_bias_128<1><<<gp, blk>>>(k, wk, bk, kh);
    gemm_bias_128<1><<<gp, blk>>>(v, wv, bv, vh);

    const int attn_smem = 4 * 64 * 68 * (int)sizeof(float);  // 69632
    cudaFuncSetAttribute(attn64, cudaFuncAttributeMaxDynamicSharedMemorySize, attn_smem);
    const dim3 ga(SEQ / 64, BATCH * NUM_HEADS);              // (32, 64)
    attn64<<<ga, blk, attn_smem>>>(qh, kh, vh, ctx);

    gemm_bias_128<0><<<gp, blk>>>(ctx, wo, bo, out);
}

// round 2
// speedup vs baseline: 1.6847x; 1.6847x over previous
#include <cuda_runtime.h>
#include <cstdint>

#define D_MODEL   1024
#define NUM_HEADS 16
#define DEPTH     64
#define BATCH     4
#define SEQ       2048
#define NROWS     (BATCH * SEQ)   // 8192

// Scratch: head-split Q/K/V [B*H, S, DEPTH] and merged context [B*S, D_MODEL]
__device__ float g_qh[(size_t)NROWS * D_MODEL];
__device__ float g_kh[(size_t)NROWS * D_MODEL];
__device__ float g_vh[(size_t)NROWS * D_MODEL];
__device__ float g_ctx[(size_t)NROWS * D_MODEL];

// ---------------------------------------------------------------------------
// helpers
// ---------------------------------------------------------------------------
__device__ __forceinline__ uint32_t f2tf(float x) {
    uint32_t u;
    asm("cvt.rna.tf32.f32 %0, %1;" : "=r"(u) : "f"(x));
    return u;
}

__device__ __forceinline__ void mma8(float* d, const uint32_t* a, const uint32_t* b) {
    asm volatile(
        "mma.sync.aligned.m16n8k8.row.col.f32.tf32.tf32.f32 "
        "{%0,%1,%2,%3}, {%4,%5,%6,%7}, {%8,%9}, {%0,%1,%2,%3};"
        : "+f"(d[0]), "+f"(d[1]), "+f"(d[2]), "+f"(d[3])
        : "r"(a[0]), "r"(a[1]), "r"(a[2]), "r"(a[3]), "r"(b[0]), "r"(b[1]));
}

__device__ __forceinline__ void cpa16(uint32_t s, const void* g) {
    asm volatile("cp.async.cg.shared.global [%0], [%1], 16;" :: "r"(s), "l"(g));
}

// ---------------------------------------------------------------------------
// 3xTF32 GEMM + bias: C = A[8192 x 1024] @ W[1024 x 1024] + b
// Block 128x128, BK=32, 256 threads (8 warps, 4x2), warp tile 32x64.
// Raw fp32 staged via cp.async (double-buffered); hi/lo tf32 split at consume.
// smem pads: A stride 36 (36%32==4 -> (4g+t) conflict-free),
//            W stride 136 (136%32==8 -> (8t+g) conflict-free).
// ---------------------------------------------------------------------------
#define AST 36
#define WST 136

template <int HEADOUT>
__global__ __launch_bounds__(256)
void gemm3x(const float* __restrict__ A, const float* __restrict__ W,
            const float* __restrict__ bias, float* __restrict__ C) {
    extern __shared__ float sm[];
    float* Ab0 = sm;
    float* Ab1 = sm + 128 * AST;
    float* Wb0 = sm + 2 * 128 * AST;
    float* Wb1 = Wb0 + 32 * WST;

    const int tid  = threadIdx.x;
    const int w    = tid >> 5;
    const int lane = tid & 31;
    const int g    = lane >> 2;
    const int t    = lane & 3;
    const int wm   = w >> 1;     // 0..3
    const int wn   = w & 1;      // 0..1
    const int row0 = blockIdx.y * 128;
    const int col0 = blockIdx.x * 128;

    // loader mapping
    const int ar = tid >> 1;            // 0..127
    const int ak = (tid & 1) * 16;      // 0 or 16
    const int wr = tid >> 3;            // 0..31
    const int wc = (tid & 7) * 16;      // 0..112

    float acc[2][8][4];
#pragma unroll
    for (int i = 0; i < 2; i++)
#pragma unroll
        for (int f = 0; f < 8; f++)
#pragma unroll
            for (int j = 0; j < 4; j++) acc[i][f][j] = 0.0f;

    // issue tile kt into buffer buf
    auto issue_tile = [&](int kt, int buf) {
        float* Ad = buf ? Ab1 : Ab0;
        float* Wd = buf ? Wb1 : Wb0;
        const float* ga = &A[(size_t)(row0 + ar) * D_MODEL + kt * 32 + ak];
        uint32_t sa = (uint32_t)__cvta_generic_to_shared(&Ad[ar * AST + ak]);
#pragma unroll
        for (int q = 0; q < 4; q++) cpa16(sa + q * 16, ga + q * 4);
        const float* gw = &W[(size_t)(kt * 32 + wr) * D_MODEL + col0 + wc];
        uint32_t sw = (uint32_t)__cvta_generic_to_shared(&Wd[wr * WST + wc]);
#pragma unroll
        for (int q = 0; q < 4; q++) cpa16(sw + q * 16, gw + q * 4);
        asm volatile("cp.async.commit_group;");
    };

    issue_tile(0, 0);

    for (int kt = 0; kt < 32; kt++) {
        if (kt + 1 < 32) {
            issue_tile(kt + 1, (kt + 1) & 1);
            asm volatile("cp.async.wait_group 1;");
        } else {
            asm volatile("cp.async.wait_group 0;");
        }
        __syncthreads();
        const float* Abuf = (kt & 1) ? Ab1 : Ab0;
        const float* Wbuf = (kt & 1) ? Wb1 : Wb0;

#pragma unroll
        for (int kk = 0; kk < 32; kk += 8) {
            uint32_t ahi[2][4], alo[2][4];
#pragma unroll
            for (int i = 0; i < 2; i++) {
                const int r = wm * 32 + i * 16 + g;
                float x0 = Abuf[r * AST + kk + t];
                float x1 = Abuf[(r + 8) * AST + kk + t];
                float x2 = Abuf[r * AST + kk + t + 4];
                float x3 = Abuf[(r + 8) * AST + kk + t + 4];
                ahi[i][0] = f2tf(x0); alo[i][0] = f2tf(x0 - __uint_as_float(ahi[i][0]));
                ahi[i][1] = f2tf(x1); alo[i][1] = f2tf(x1 - __uint_as_float(ahi[i][1]));
                ahi[i][2] = f2tf(x2); alo[i][2] = f2tf(x2 - __uint_as_float(ahi[i][2]));
                ahi[i][3] = f2tf(x3); alo[i][3] = f2tf(x3 - __uint_as_float(ahi[i][3]));
            }
#pragma unroll
            for (int f = 0; f < 8; f++) {
                const int n = wn * 64 + f * 8 + g;
                float y0 = Wbuf[(kk + t) * WST + n];
                float y1 = Wbuf[(kk + t + 4) * WST + n];
                uint32_t bhi[2], blo[2];
                bhi[0] = f2tf(y0); blo[0] = f2tf(y0 - __uint_as_float(bhi[0]));
                bhi[1] = f2tf(y1); blo[1] = f2tf(y1 - __uint_as_float(bhi[1]));
#pragma unroll
                for (int i = 0; i < 2; i++) {
                    mma8(acc[i][f], ahi[i], bhi);
                    mma8(acc[i][f], ahi[i], blo);
                    mma8(acc[i][f], alo[i], bhi);
                }
            }
        }
        __syncthreads();
    }

    // epilogue: bias + store (float2 per fragment row-pair)
#pragma unroll
    for (int i = 0; i < 2; i++) {
        const int r0 = row0 + wm * 32 + i * 16 + g;
        const int r1 = r0 + 8;
#pragma unroll
        for (int f = 0; f < 8; f++) {
            const int c = col0 + wn * 64 + f * 8 + 2 * t;
            float2 bb = *(const float2*)&bias[c];
            float2 v01 = make_float2(acc[i][f][0] + bb.x, acc[i][f][1] + bb.y);
            float2 v23 = make_float2(acc[i][f][2] + bb.x, acc[i][f][3] + bb.y);
            if (HEADOUT) {
                const int h = c >> 6, d = c & 63;
                const int b0_ = r0 >> 11, s0 = r0 & (SEQ - 1);
                const int b1_ = r1 >> 11, s1 = r1 & (SEQ - 1);
                *(float2*)&C[((size_t)(b0_ * NUM_HEADS + h) * SEQ + s0) * DEPTH + d] = v01;
                *(float2*)&C[((size_t)(b1_ * NUM_HEADS + h) * SEQ + s1) * DEPTH + d] = v23;
            } else {
                *(float2*)&C[(size_t)r0 * D_MODEL + c] = v01;
                *(float2*)&C[(size_t)r1 * D_MODEL + c] = v23;
            }
        }
    }
}

// ---------------------------------------------------------------------------
// Flash attention, tf32 mma. Block = 128 queries (8 warps, 16 rows each),
// key tiles of 64, dh = 64. Online softmax on mma fragments.
// smem: Ps[128][68] (doubles as Qs at start), Ks[64][68], Vs[64][72].
// ---------------------------------------------------------------------------
__global__ __launch_bounds__(256)
void attn_mma(const float* __restrict__ qh, const float* __restrict__ kh,
              const float* __restrict__ vh) {
    extern __shared__ float sm[];
    float* Ps = sm;                    // [128][68]  (Qs at start)
    float* Ks = sm + 128 * 68;         // [64][68]
    float* Vs = Ks + 64 * 68;          // [64][72]

    const int tid  = threadIdx.x;
    const int w    = tid >> 5;
    const int lane = tid & 31;
    const int g    = lane >> 2;
    const int t    = lane & 3;
    const int bh   = blockIdx.y;
    const int q0   = blockIdx.x * 128;

    const float* Qb = qh + (size_t)bh * SEQ * DEPTH;
    const float* Kb = kh + (size_t)bh * SEQ * DEPTH;
    const float* Vb = vh + (size_t)bh * SEQ * DEPTH;

    // Load Q tile (tf32) into Ps area
    {
        const int r = tid >> 1, co = (tid & 1) * 32;
        const float* gp = &Qb[(size_t)(q0 + r) * DEPTH + co];
#pragma unroll
        for (int qd = 0; qd < 8; qd++) {
            float4 v = *(const float4*)&gp[qd * 4];
            float4 o;
            o.x = __uint_as_float(f2tf(v.x));
            o.y = __uint_as_float(f2tf(v.y));
            o.z = __uint_as_float(f2tf(v.z));
            o.w = __uint_as_float(f2tf(v.w));
            *(float4*)&Ps[r * 68 + co + qd * 4] = o;
        }
    }
    __syncthreads();

    // Pull Q fragments to registers (A frags, m16n8k8 over dh)
    uint32_t Qf[8][4];
    {
        const int r = w * 16 + g;
#pragma unroll
        for (int kk = 0; kk < 8; kk++) {
            Qf[kk][0] = __float_as_uint(Ps[r * 68 + kk * 8 + t]);
            Qf[kk][1] = __float_as_uint(Ps[(r + 8) * 68 + kk * 8 + t]);
            Qf[kk][2] = __float_as_uint(Ps[r * 68 + kk * 8 + t + 4]);
            Qf[kk][3] = __float_as_uint(Ps[(r + 8) * 68 + kk * 8 + t + 4]);
        }
    }
    __syncthreads();   // Ps may now be reused for P

    float Of[8][4];
#pragma unroll
    for (int f = 0; f < 8; f++)
#pragma unroll
        for (int j = 0; j < 4; j++) Of[f][j] = 0.0f;
    float m0 = -1e30f, m1 = -1e30f, l0 = 0.0f, l1 = 0.0f;

    for (int k0 = 0; k0 < SEQ; k0 += 64) {
        // Load K, V tiles (tf32)
        {
            const int r = tid >> 2, co = (tid & 3) * 16;
#pragma unroll
            for (int qd = 0; qd < 4; qd++) {
                float4 kv = *(const float4*)&Kb[(size_t)(k0 + r) * DEPTH + co + qd * 4];
                float4 ko;
                ko.x = __uint_as_float(f2tf(kv.x));
                ko.y = __uint_as_float(f2tf(kv.y));
                ko.z = __uint_as_float(f2tf(kv.z));
                ko.w = __uint_as_float(f2tf(kv.w));
                *(float4*)&Ks[r * 68 + co + qd * 4] = ko;
                float4 vv = *(const float4*)&Vb[(size_t)(k0 + r) * DEPTH + co + qd * 4];
                float4 vo;
                vo.x = __uint_as_float(f2tf(vv.x));
                vo.y = __uint_as_float(f2tf(vv.y));
                vo.z = __uint_as_float(f2tf(vv.z));
                vo.w = __uint_as_float(f2tf(vv.w));
                *(float4*)&Vs[r * 72 + co + qd * 4] = vo;
            }
        }
        __syncthreads();

        // S = Q K^T
        float Sc[8][4];
#pragma unroll
        for (int f = 0; f < 8; f++)
#pragma unroll
            for (int j = 0; j < 4; j++) Sc[f][j] = 0.0f;

#pragma unroll
        for (int kk = 0; kk < 8; kk++) {
#pragma unroll
            for (int f = 0; f < 8; f++) {
                uint32_t b[2];
                b[0] = __float_as_uint(Ks[(f * 8 + g) * 68 + kk * 8 + t]);
                b[1] = __float_as_uint(Ks[(f * 8 + g) * 68 + kk * 8 + t + 4]);
                mma8(Sc[f], Qf[kk], b);
            }
        }

        // scale + online softmax
        float mx0 = -1e30f, mx1 = -1e30f;
#pragma unroll
        for (int f = 0; f < 8; f++) {
            Sc[f][0] *= 0.125f; Sc[f][1] *= 0.125f;
            Sc[f][2] *= 0.125f; Sc[f][3] *= 0.125f;
            mx0 = fmaxf(mx0, fmaxf(Sc[f][0], Sc[f][1]));
            mx1 = fmaxf(mx1, fmaxf(Sc[f][2], Sc[f][3]));
        }
        mx0 = fmaxf(mx0, __shfl_xor_sync(0xffffffffu, mx0, 1));
        mx0 = fmaxf(mx0, __shfl_xor_sync(0xffffffffu, mx0, 2));
        mx1 = fmaxf(mx1, __shfl_xor_sync(0xffffffffu, mx1, 1));
        mx1 = fmaxf(mx1, __shfl_xor_sync(0xffffffffu, mx1, 2));

        const float mn0 = fmaxf(m0, mx0);
        const float mn1 = fmaxf(m1, mx1);
        const float corr0 = __expf(m0 - mn0);
        const float corr1 = __expf(m1 - mn1);
        m0 = mn0; m1 = mn1;

        float sum0 = 0.0f, sum1 = 0.0f;
        const int r = w * 16 + g;
#pragma unroll
        for (int f = 0; f < 8; f++) {
            float p0 = __expf(Sc[f][0] - m0);
            float p1 = __expf(Sc[f][1] - m0);
            float p2 = __expf(Sc[f][2] - m1);
            float p3 = __expf(Sc[f][3] - m1);
            sum0 += p0 + p1;
            sum1 += p2 + p3;
            Of[f][0] *= corr0; Of[f][1] *= corr0;
            Of[f][2] *= corr1; Of[f][3] *= corr1;
            float2 w01 = make_float2(__uint_as_float(f2tf(p0)), __uint_as_float(f2tf(p1)));
            float2 w23 = make_float2(__uint_as_float(f2tf(p2)), __uint_as_float(f2tf(p3)));
            *(float2*)&Ps[r * 68 + f * 8 + 2 * t] = w01;
            *(float2*)&Ps[(r + 8) * 68 + f * 8 + 2 * t] = w23;
        }
        sum0 += __shfl_xor_sync(0xffffffffu, sum0, 1);
        sum0 += __shfl_xor_sync(0xffffffffu, sum0, 2);
        sum1 += __shfl_xor_sync(0xffffffffu, sum1, 1);
        sum1 += __shfl_xor_sync(0xffffffffu, sum1, 2);
        l0 = l0 * corr0 + sum0;
        l1 = l1 * corr1 + sum1;

        __syncwarp();   // Ps rows are warp-private; order STS before LDS

        // O += P V
#pragma unroll
        for (int kk = 0; kk < 8; kk++) {
            uint32_t a[4];
            a[0] = __float_as_uint(Ps[r * 68 + kk * 8 + t]);
            a[1] = __float_as_uint(Ps[(r + 8) * 68 + kk * 8 + t]);
            a[2] = __float_as_uint(Ps[r * 68 + kk * 8 + t + 4]);
            a[3] = __float_as_uint(Ps[(r + 8) * 68 + kk * 8 + t + 4]);
#pragma unroll
            for (int f = 0; f < 8; f++) {
                uint32_t b[2];
                b[0] = __float_as_uint(Vs[(kk * 8 + t) * 72 + f * 8 + g]);
                b[1] = __float_as_uint(Vs[(kk * 8 + t + 4) * 72 + f * 8 + g]);
                mma8(Of[f], a, b);
            }
        }
        __syncthreads();  // all warps done with Ks/Vs/Ps before next tile load
    }

    // Finalize
    const int b  = bh >> 4;
    const int h  = bh & 15;
    const float inv0 = 1.0f / l0;
    const float inv1 = 1.0f / l1;
    const int r0 = q0 + w * 16 + g;
#pragma unroll
    for (int f = 0; f < 8; f++) {
        const int c = h * 64 + f * 8 + 2 * t;
        *(float2*)&g_ctx[(size_t)(b * SEQ + r0) * D_MODEL + c] =
            make_float2(Of[f][0] * inv0, Of[f][1] * inv0);
        *(float2*)&g_ctx[(size_t)(b * SEQ + r0 + 8) * D_MODEL + c] =
            make_float2(Of[f][2] * inv1, Of[f][3] * inv1);
    }
}

// ---------------------------------------------------------------------------
extern "C" void kernel_launch(void* const* d_in, const int* in_sizes, int n_in,
                              void* d_out, int out_size) {
    const float* v  = (const float*)d_in[0];
    const float* k  = (const float*)d_in[1];
    const float* q  = (const float*)d_in[2];
    const float* wq = (const float*)d_in[3];
    const float* bq = (const float*)d_in[4];
    const float* wk = (const float*)d_in[5];
    const float* bk = (const float*)d_in[6];
    const float* wv = (const float*)d_in[7];
    const float* bv = (const float*)d_in[8];
    const float* wo = (const float*)d_in[9];
    const float* bo = (const float*)d_in[10];
    float* out = (float*)d_out;

    float *qh, *kh, *vh, *ctx;
    cudaGetSymbolAddress((void**)&qh, g_qh);
    cudaGetSymbolAddress((void**)&kh, g_kh);
    cudaGetSymbolAddress((void**)&vh, g_vh);
    cudaGetSymbolAddress((void**)&ctx, g_ctx);

    const int gemm_smem = (2 * 128 * AST + 2 * 32 * WST) * (int)sizeof(float); // 71680
    const int attn_smem = (128 * 68 + 64 * 68 + 64 * 72) * (int)sizeof(float); // 70656

    cudaFuncSetAttribute(gemm3x<1>, cudaFuncAttributeMaxDynamicSharedMemorySize, gemm_smem);
    cudaFuncSetAttribute(gemm3x<0>, cudaFuncAttributeMaxDynamicSharedMemorySize, gemm_smem);
    cudaFuncSetAttribute(attn_mma,  cudaFuncAttributeMaxDynamicSharedMemorySize, attn_smem);

    const dim3 blk(256);
    const dim3 gp(D_MODEL / 128, NROWS / 128);   // (8, 64)

    gemm3x<1><<<gp, blk, gemm_smem>>>(q, wq, bq, qh);
    gemm3x<1><<<gp, blk, gemm_smem>>>(k, wk, bk, kh);
    gemm3x<1><<<gp, blk, gemm_smem>>>(v, wv, bv, vh);

    const dim3 ga(SEQ / 128, BATCH * NUM_HEADS);  // (16, 64)
    attn_mma<<<ga, blk, attn_smem>>>(qh, kh, vh);

    gemm3x<0><<<gp, blk, gemm_smem>>>(ctx, wo, bo, out);
}